// round 1
// baseline (speedup 1.0000x reference)
#include <cuda_runtime.h>
#include <stdint.h>

#define NMAX 8192
#define WORDS (NMAX/32)   /* 256 */
#define W_IMG 1920.0f
#define H_IMG 1080.0f

// ---------------- device scratch (static: no allocation allowed) ----------------
__device__ uint32_t g_adjT[WORDS][NMAX];          // 8 MB, transposed adjacency bits
__device__ unsigned long long g_sortkey[NMAX];
__device__ float g_bx1[NMAX], g_by1[NMAX], g_bx2[NMAX], g_by2[NMAX];
__device__ float g_s[NMAX], g_area[NMAX];
__device__ uint32_t g_head[WORDS];
__device__ int g_cluster[NMAX];
__device__ int g_cnt[NMAX];
__device__ float g_prob[NMAX];
__device__ uint32_t g_y2bits[NMAX];
__device__ int g_first[NMAX];
__device__ int g_nm;

// ---------------- K0: prep (sort keys, init reductions, num_models) -------------
__global__ void k_prep(const float* __restrict__ scores, const void* __restrict__ nmp, int n)
{
    int i = blockIdx.x * blockDim.x + threadIdx.x;
    if (i < n) {
        uint32_t sb = __float_as_uint(scores[i]);   // scores > 0 always
        g_sortkey[i] = (((unsigned long long)(~sb)) << 32) | (uint32_t)i;
        g_cnt[i] = 0; g_prob[i] = 0.0f; g_y2bits[i] = 0u; g_first[i] = n;
    }
    if (i == 0) {
        int iv = ((const int*)nmp)[0];
        float fv = ((const float*)nmp)[0];
        g_nm = (iv > 0 && iv < 1000000) ? iv : (int)fv;   // robust int/float sniff
    }
}

// ---------------- K1: single-block bitonic sort of 64-bit keys ------------------
__global__ void k_sort(int n)
{
    extern __shared__ unsigned long long sk[];
    int tid = threadIdx.x;
    for (int i = tid; i < n; i += blockDim.x) sk[i] = g_sortkey[i];
    __syncthreads();
    for (int k = 2; k <= n; k <<= 1) {
        for (int j = k >> 1; j > 0; j >>= 1) {
            for (int t = tid; t < n; t += blockDim.x) {
                int x = t ^ j;
                if (x > t) {
                    unsigned long long a = sk[t], b = sk[x];
                    bool up = ((t & k) == 0);
                    if ((a > b) == up) { sk[t] = b; sk[x] = a; }
                }
            }
            __syncthreads();
        }
    }
    for (int i = tid; i < n; i += blockDim.x) g_sortkey[i] = sk[i];
}

// ---------------- K2: gather in sorted order, clip, area ------------------------
__global__ void k_gather(const float* __restrict__ boxes, const float* __restrict__ scores, int n)
{
    int i = blockIdx.x * blockDim.x + threadIdx.x;
    if (i >= n) return;
    int o = (int)(g_sortkey[i] & 0xffffffffULL);
    float x1 = boxes[o * 4 + 0], y1 = boxes[o * 4 + 1];
    float x2 = boxes[o * 4 + 2], y2 = boxes[o * 4 + 3];
    x1 = fminf(fmaxf(x1, 0.0f), W_IMG);
    y1 = fminf(fmaxf(y1, 0.0f), H_IMG);
    x2 = fminf(fmaxf(x2, 0.0f), W_IMG);
    y2 = fminf(fmaxf(y2, 0.0f), H_IMG);
    g_bx1[i] = x1; g_by1[i] = y1; g_bx2[i] = x2; g_by2[i] = y2;
    g_s[i] = scores[o];
    g_area[i] = ((x2 - x1) + 1.0f) * ((y2 - y1) + 1.0f);
}

// ---------------- K3: lower-triangle adjacency bits (transposed store) ----------
// block = 256 threads (8 warps). col tile = 1024 cols, row tile = 128 rows.
__global__ void k_adj(int n)
{
    int colBase = blockIdx.x * 1024;
    int rowBase = blockIdx.y * 128;
    if (colBase > rowBase + 127) return;            // strictly above diagonal

    __shared__ float cx1[1024], cy1[1024], cx2[1024], cy2[1024], ca[1024];
    __shared__ float rx1[128],  ry1[128],  rx2[128],  ry2[128],  ra[128];

    for (int t = threadIdx.x; t < 1024; t += 256) {
        int c = colBase + t; if (c >= n) c = n - 1;
        cx1[t] = g_bx1[c]; cy1[t] = g_by1[c]; cx2[t] = g_bx2[c]; cy2[t] = g_by2[c]; ca[t] = g_area[c];
    }
    for (int t = threadIdx.x; t < 128; t += 256) {
        int r = rowBase + t; if (r >= n) r = n - 1;
        rx1[t] = g_bx1[r]; ry1[t] = g_by1[r]; rx2[t] = g_bx2[r]; ry2[t] = g_by2[r]; ra[t] = g_area[r];
    }
    __syncthreads();

    int warp = threadIdx.x >> 5, lane = threadIdx.x & 31;

    for (int wi = 0; wi < 32; wi++) {
        int colWordBase = colBase + wi * 32;
        int gword = (colBase >> 5) + wi;
        int cIdx = wi * 32 + lane;
        float x1b = cx1[cIdx], y1b = cy1[cIdx], x2b = cx2[cIdx], y2b = cy2[cIdx], ab = ca[cIdx];

        #pragma unroll 4
        for (int rr = 0; rr < 16; rr++) {
            int rloc = warp * 16 + rr;
            int row = rowBase + rloc;
            if (colWordBase > row) continue;        // uniform per warp
            float x1a = rx1[rloc], y1a = ry1[rloc], x2a = rx2[rloc], y2a = ry2[rloc], aa = ra[rloc];
            float ix1 = fmaxf(x1a, x1b);
            float iy1 = fmaxf(y1a, y1b);
            float ix2 = fminf(x2a, x2b);
            float iy2 = fminf(y2a, y2b);
            float w = fmaxf((ix2 - ix1) + 1.0f, 0.0f);
            float h = fmaxf((iy2 - iy1) + 1.0f, 0.0f);
            float inter = w * h;
            float den = (aa + ab) - inter;
            bool adjf = (inter + inter) > den;      // == real iou > 0.5
            unsigned bits = __ballot_sync(0xffffffffu, adjf);
            if (lane == 0) g_adjT[gword][row] = bits;
        }
    }
}

// ---------------- K4: head scan (single block, chunked 128 columns) -------------
__global__ void k_scan(int n)
{
    __shared__ uint32_t sup[WORDS];
    __shared__ uint32_t headAll[WORDS];
    __shared__ uint32_t la[128][4];
    __shared__ uint32_t actw[4], confw[4], headc[4];
    __shared__ int anyhead;

    int tid = threadIdx.x;
    if (tid < WORDS) { sup[tid] = 0u; headAll[tid] = 0u; }
    __syncthreads();

    int chunks = n >> 7;
    for (int c = 0; c < chunks; c++) {
        int base = c << 7;
        bool active = false;
        if (tid < 128) {
            int j = base + tid;
            la[tid][0] = g_adjT[4 * c + 0][j];
            la[tid][1] = g_adjT[4 * c + 1][j];
            la[tid][2] = g_adjT[4 * c + 2][j];
            la[tid][3] = g_adjT[4 * c + 3][j];
            active = ((sup[j >> 5] >> (j & 31)) & 1u) == 0u;
            unsigned b = __ballot_sync(0xffffffffu, active);
            if ((tid & 31) == 0) actw[tid >> 5] = b;
        }
        __syncthreads();
        if (tid < 128) {
            int k = tid >> 5, b = tid & 31;
            uint32_t bl = (b == 0) ? 0u : ((1u << b) - 1u);
            uint32_t hit = 0u;
            #pragma unroll
            for (int kk = 0; kk < 4; kk++) {
                uint32_t am = (kk < k) ? actw[kk] : ((kk == k) ? (actw[kk] & bl) : 0u);
                hit |= la[tid][kk] & am;
            }
            bool conflict = active && (hit != 0u);
            unsigned cb = __ballot_sync(0xffffffffu, conflict);
            if ((tid & 31) == 0) confw[tid >> 5] = cb;
        }
        __syncthreads();
        if (tid == 0) {
            uint32_t h[4];
            #pragma unroll
            for (int k = 0; k < 4; k++) h[k] = actw[k] & ~confw[k];   // non-conflicted actives are heads
            for (int k = 0; k < 4; k++) {
                uint32_t m = confw[k];
                while (m) {
                    int b = __ffs(m) - 1; m &= m - 1;
                    int jj = k * 32 + b;
                    uint32_t hit = 0u;
                    for (int kk = 0; kk < k; kk++) hit |= la[jj][kk] & h[kk];
                    uint32_t bl = (b == 0) ? 0u : ((1u << b) - 1u);
                    hit |= la[jj][k] & h[k] & bl;
                    if (hit == 0u) h[k] |= 1u << b;
                }
            }
            anyhead = (int)(h[0] | h[1] | h[2] | h[3]);
            #pragma unroll
            for (int k = 0; k < 4; k++) { headc[k] = h[k]; headAll[4 * c + k] = h[k]; }
        }
        __syncthreads();
        if (anyhead) {
            uint32_t h0 = headc[0], h1 = headc[1], h2 = headc[2], h3 = headc[3];
            for (int j = base + 128 + tid; j < n; j += blockDim.x) {
                uint32_t wv = sup[j >> 5];
                if ((wv >> (j & 31)) & 1u) continue;
                uint32_t m = (g_adjT[4 * c + 0][j] & h0) | (g_adjT[4 * c + 1][j] & h1)
                           | (g_adjT[4 * c + 2][j] & h2) | (g_adjT[4 * c + 3][j] & h3);
                if (m) atomicOr(&sup[j >> 5], 1u << (j & 31));
            }
        }
        __syncthreads();
    }
    if (tid < WORDS) g_head[tid] = headAll[tid];
}

// ---------------- K5: cluster assignment + segment reductions -------------------
__global__ void k_assign(int n)
{
    __shared__ uint32_t hh[WORDS];
    for (int t = threadIdx.x; t < WORDS; t += blockDim.x) hh[t] = g_head[t];
    __syncthreads();
    int j = blockIdx.x * blockDim.x + threadIdx.x;
    if (j >= n) return;
    int cfound = j;
    int wmax = j >> 5;
    for (int w = 0; w <= wmax; w++) {
        uint32_t m = g_adjT[w][j] & hh[w];
        if (m) { cfound = w * 32 + __ffs(m) - 1; break; }   // min adjacent head (<= j guaranteed)
    }
    g_cluster[j] = cfound;
    atomicAdd(&g_cnt[cfound], 1);
    atomicAdd(&g_prob[cfound], g_s[j]);
    atomicMax(&g_y2bits[cfound], __float_as_uint(g_by2[j]));  // by2 >= 0 -> bit-ordered
}

// ---------------- K6: first pick per cluster ------------------------------------
__global__ void k_first(int n)
{
    int j = blockIdx.x * blockDim.x + threadIdx.x;
    if (j >= n) return;
    int c = g_cluster[j];
    float mx = __uint_as_float(g_y2bits[c]);
    if (g_by2[j] >= mx) atomicMin(&g_first[c], j);
}

// ---------------- K7: write output ----------------------------------------------
__global__ void k_out(float* __restrict__ out, int n, int out_size)
{
    int i = blockIdx.x * blockDim.x + threadIdx.x;
    if (i < n) {
        int c = g_cluster[i];
        float nmf = (float)g_nm;
        bool keep = (i == g_first[c]) && ((float)g_cnt[c] >= nmf / 3.0f);
        float so = g_prob[c] / nmf;
        out[i * 5 + 0] = keep ? g_bx1[i] : 0.0f;
        out[i * 5 + 1] = keep ? g_by1[i] : 0.0f;
        out[i * 5 + 2] = keep ? g_bx2[i] : 0.0f;
        out[i * 5 + 3] = keep ? g_by2[i] : 0.0f;
        out[i * 5 + 4] = keep ? so : 0.0f;
        if (out_size >= 6 * n) out[5 * n + i] = keep ? 1.0f : 0.0f;
    }
    // zero any tail beyond 6n (buffer is poisoned by harness)
    int stride = gridDim.x * blockDim.x;
    for (int t = 6 * n + i; t < out_size; t += stride) out[t] = 0.0f;
}

// ---------------- launcher -------------------------------------------------------
extern "C" void kernel_launch(void* const* d_in, const int* in_sizes, int n_in,
                              void* d_out, int out_size)
{
    const float* boxes  = (const float*)d_in[0];
    const float* scores = (const float*)d_in[1];
    const void*  nmp    = d_in[2];
    int n = in_sizes[1];
    if (n > NMAX) n = NMAX;

    cudaFuncSetAttribute(k_sort, cudaFuncAttributeMaxDynamicSharedMemorySize,
                         (int)(NMAX * sizeof(unsigned long long)));

    int nb = (n + 255) / 256;
    k_prep<<<nb, 256>>>(scores, nmp, n);
    k_sort<<<1, 1024, n * sizeof(unsigned long long)>>>(n);
    k_gather<<<nb, 256>>>(boxes, scores, n);
    dim3 agrid((n + 1023) / 1024, (n + 127) / 128);
    k_adj<<<agrid, 256>>>(n);
    k_scan<<<1, 1024>>>(n);
    k_assign<<<nb, 256>>>(n);
    k_first<<<nb, 256>>>(n);
    k_out<<<nb, 256>>>((float*)d_out, n, out_size);
}

// round 2
// speedup vs baseline: 1.8171x; 1.8171x over previous
#include <cuda_runtime.h>
#include <stdint.h>

#define NMAX 8192
#define WORDS (NMAX/32)   /* 256 */
#define NZW   (WORDS/32)  /* 8 */
#define W_IMG 1920.0f
#define H_IMG 1080.0f

// ---------------- device scratch ----------------
__device__ uint32_t g_adjT[WORDS][NMAX];      // transposed adjacency bits (sparse: only nonzero words written)
__device__ uint32_t g_nz[NZW][NMAX];          // per-row bitmap of nonzero adjacency words
__device__ unsigned long long g_key[NMAX];
__device__ int g_rank[NMAX];
__device__ float4 g_abox[NMAX];               // clipped x1,y1,x2+1,y2+1 (for IoU)
__device__ float4 g_obox[NMAX];               // clipped x1,y1,x2,y2 (for output)
__device__ float g_s[NMAX], g_area[NMAX], g_by2[NMAX];
__device__ uint32_t g_head[WORDS];
__device__ int g_cluster[NMAX];
__device__ int g_cnt[NMAX];
__device__ float g_prob[NMAX];
__device__ uint32_t g_y2bits[NMAX];
__device__ int g_first[NMAX];
__device__ int g_nm;

// ---------------- K0: prep ----------------
__global__ void k_prep(const float* __restrict__ scores, const void* __restrict__ nmp, int n)
{
    int i = blockIdx.x * blockDim.x + threadIdx.x;
    if (i < n) {
        uint32_t sb = __float_as_uint(scores[i]);       // scores > 0
        g_key[i] = (((unsigned long long)(~sb)) << 32) | (uint32_t)i;
        g_rank[i] = 0;
        g_cnt[i] = 0; g_prob[i] = 0.0f; g_y2bits[i] = 0u; g_first[i] = n;
        #pragma unroll
        for (int w = 0; w < NZW; w++) g_nz[w][i] = 0u;
    }
    if (i == 0) {
        int iv = ((const int*)nmp)[0];
        float fv = ((const float*)nmp)[0];
        g_nm = (iv > 0 && iv < 1000000) ? iv : (int)fv;
    }
}

// ---------------- K1: O(n^2) rank sort (partial counts, massively parallel) ----
__global__ void k_rank(int n)
{
    __shared__ unsigned long long sk[1024];
    int base = blockIdx.y * 1024;
    for (int t = threadIdx.x; t < 1024; t += 256)
        sk[t] = (base + t < n) ? g_key[base + t] : 0xFFFFFFFFFFFFFFFFULL;
    __syncthreads();
    int i = blockIdx.x * 256 + threadIdx.x;
    if (i >= n) return;
    unsigned long long a = g_key[i];
    int cnt = 0;
    #pragma unroll 8
    for (int q = 0; q < 1024; q++) cnt += (sk[q] < a);
    if (cnt) atomicAdd(&g_rank[i], cnt);
}

// ---------------- K2: gather/scatter into sorted order, clip, area -------------
__global__ void k_gather(const float* __restrict__ boxes, const float* __restrict__ scores, int n)
{
    int i = blockIdx.x * blockDim.x + threadIdx.x;
    if (i >= n) return;
    int r = g_rank[i];
    float x1 = boxes[i * 4 + 0], y1 = boxes[i * 4 + 1];
    float x2 = boxes[i * 4 + 2], y2 = boxes[i * 4 + 3];
    x1 = fminf(fmaxf(x1, 0.0f), W_IMG);
    y1 = fminf(fmaxf(y1, 0.0f), H_IMG);
    x2 = fminf(fmaxf(x2, 0.0f), W_IMG);
    y2 = fminf(fmaxf(y2, 0.0f), H_IMG);
    g_obox[r] = make_float4(x1, y1, x2, y2);
    g_abox[r] = make_float4(x1, y1, x2 + 1.0f, y2 + 1.0f);
    g_by2[r] = y2;
    g_s[r] = scores[i];
    g_area[r] = ((x2 - x1) + 1.0f) * ((y2 - y1) + 1.0f);
}

// ---------------- K3: lower-triangle adjacency (triangular grid, sparse store) -
// tile = 128 rows x 1024 cols; block 256 threads (8 warps, 16 rows/warp)
__global__ void k_adj(int n)
{
    int rem = blockIdx.x, rt = 0;
    for (;;) { int cnt = (rt >> 3) + 1; if (rem < cnt) break; rem -= cnt; rt++; }
    int rowBase = rt * 128, colBase = rem * 1024;

    __shared__ float4 cb[1024]; __shared__ float ca[1024];
    __shared__ float4 rb[128];  __shared__ float ra[128];

    for (int t = threadIdx.x; t < 1024; t += 256) {
        int c = colBase + t;
        if (c < n) { cb[t] = g_abox[c]; ca[t] = g_area[c]; }
        else       { cb[t] = make_float4(2e9f, 2e9f, -2e9f, -2e9f); ca[t] = 1.0f; }
    }
    for (int t = threadIdx.x; t < 128; t += 256) {
        int r = rowBase + t; if (r >= n) r = n - 1;
        rb[t] = g_abox[r]; ra[t] = g_area[r];
    }
    __syncthreads();

    int warp = threadIdx.x >> 5, lane = threadIdx.x & 31;
    int rloc0 = warp * 16;

    for (int grp = 0; grp < 4; grp++) {
        int rl = rloc0 + grp * 4;
        float4 A0 = rb[rl+0], A1 = rb[rl+1], A2 = rb[rl+2], A3 = rb[rl+3];
        float a0 = ra[rl+0], a1 = ra[rl+1], a2 = ra[rl+2], a3 = ra[rl+3];
        int row0 = rowBase + rl;
        for (int wi = 0; wi < 32; wi++) {
            int cwb = colBase + wi * 32;
            if (cwb > row0 + 3) continue;              // fully above diagonal
            float4 B = cb[wi * 32 + lane];
            float ab = ca[wi * 32 + lane];
            int gw = (colBase >> 5) + wi;
            #pragma unroll
            for (int k = 0; k < 4; k++) {
                int row = row0 + k;
                if (cwb > row || row >= n) continue;   // uniform across warp
                float4 A = (k == 0) ? A0 : (k == 1) ? A1 : (k == 2) ? A2 : A3;
                float aa = (k == 0) ? a0 : (k == 1) ? a1 : (k == 2) ? a2 : a3;
                float w = fmaxf(fminf(A.z, B.z) - fmaxf(A.x, B.x), 0.0f);
                float h = fmaxf(fminf(A.w, B.w) - fmaxf(A.y, B.y), 0.0f);
                float inter = w * h;
                float den = (aa + ab) - inter;
                unsigned bits = __ballot_sync(0xffffffffu, inter + inter > den);
                if (lane == 0 && bits) {
                    g_adjT[gw][row] = bits;
                    atomicOr(&g_nz[gw >> 5][row], 1u << (gw & 31));
                }
            }
        }
    }
}

// ---------------- K4: head scan (single block; warp0 heads, others prefetch) ---
__global__ void k_scan(int n)
{
    __shared__ uint32_t sup[WORDS];
    __shared__ uint32_t headAll[WORDS];
    __shared__ uint32_t la[2][128][4];
    __shared__ uint32_t hc[4];
    __shared__ uint32_t hnzs;

    int tid = threadIdx.x;
    for (int t = tid; t < WORDS; t += blockDim.x) { sup[t] = 0u; headAll[t] = 0u; }
    // preload chunk 0 rows
    for (int t = tid; t < 512; t += blockDim.x) {
        int row = t & 127, kk = t >> 7;
        la[0][row][kk] = (row < n) ? g_adjT[kk][row] : 0u;
    }
    __syncthreads();

    int chunks = (n + 127) >> 7;
    for (int c = 0; c < chunks; c++) {
        int base = c << 7;
        int buf = c & 1;
        if (tid < 32) {
            uint32_t aw[4], cw[4], myact[4];
            uint32_t lrow[4][4];
            #pragma unroll
            for (int k = 0; k < 4; k++) {
                int j = base + k * 32 + tid;
                #pragma unroll
                for (int kk = 0; kk < 4; kk++) lrow[k][kk] = la[buf][k * 32 + tid][kk];
                bool act = (j < n) && (((sup[j >> 5] >> (j & 31)) & 1u) == 0u);
                aw[k] = __ballot_sync(0xffffffffu, act);
                myact[k] = act ? 1u : 0u;
            }
            uint32_t below = (tid == 0) ? 0u : ((1u << tid) - 1u);
            #pragma unroll
            for (int k = 0; k < 4; k++) {
                uint32_t hit = 0u;
                #pragma unroll
                for (int kk = 0; kk < 4; kk++) {
                    uint32_t am = (kk < k) ? aw[kk] : ((kk == k) ? (aw[kk] & below) : 0u);
                    hit |= lrow[k][kk] & am;
                }
                cw[k] = __ballot_sync(0xffffffffu, myact[k] && hit);
            }
            __syncwarp();
            if (tid == 0) {
                uint32_t h[4];
                #pragma unroll
                for (int k = 0; k < 4; k++) h[k] = aw[k] & ~cw[k];
                for (int k = 0; k < 4; k++) {
                    uint32_t m = cw[k];
                    while (m) {
                        int b = __ffs(m) - 1; m &= m - 1;
                        int jj = k * 32 + b;
                        uint32_t hit = 0u;
                        for (int kk = 0; kk < k; kk++) hit |= la[buf][jj][kk] & h[kk];
                        uint32_t bl = (b == 0) ? 0u : ((1u << b) - 1u);
                        hit |= la[buf][jj][k] & h[k] & bl;
                        if (!hit) h[k] |= 1u << b;
                    }
                }
                uint32_t hm = 0u;
                #pragma unroll
                for (int k = 0; k < 4; k++) {
                    hc[k] = h[k]; headAll[4 * c + k] = h[k];
                    if (h[k]) hm |= 1u << k;
                }
                hnzs = hm;
            }
        } else if (c + 1 < chunks) {
            // prefetch next chunk's row words while warp0 resolves heads
            int t = tid - 32;
            if (t < 512) {
                int row = t & 127, kk = t >> 7;
                int j = base + 128 + row;
                la[buf ^ 1][row][kk] = (j < n) ? g_adjT[4 * (c + 1) + kk][j] : 0u;
            }
        }
        __syncthreads();
        uint32_t hmask = hnzs;
        if (hmask) {
            uint32_t h0 = hc[0], h1 = hc[1], h2 = hc[2], h3 = hc[3];
            int sh = (c & 7) * 4;
            for (int j = base + 128 + tid; j < n; j += blockDim.x) {
                if ((sup[j >> 5] >> (j & 31)) & 1u) continue;
                uint32_t f = (g_nz[c >> 3][j] >> sh) & hmask;
                if (!f) continue;
                uint32_t m = 0u;
                if (f & 1u) m |= g_adjT[4 * c + 0][j] & h0;
                if (f & 2u) m |= g_adjT[4 * c + 1][j] & h1;
                if (f & 4u) m |= g_adjT[4 * c + 2][j] & h2;
                if (f & 8u) m |= g_adjT[4 * c + 3][j] & h3;
                if (m) atomicOr(&sup[j >> 5], 1u << (j & 31));
            }
        }
        __syncthreads();
    }
    for (int t = tid; t < WORDS; t += blockDim.x) g_head[t] = headAll[t];
}

// ---------------- K5: cluster assignment + reductions (nz-accelerated) ---------
__global__ void k_assign(int n)
{
    __shared__ uint32_t hh[WORDS];
    for (int t = threadIdx.x; t < WORDS; t += blockDim.x) hh[t] = g_head[t];
    __syncthreads();
    int j = blockIdx.x * blockDim.x + threadIdx.x;
    if (j >= n) return;
    int wmax = j >> 5;
    int cfound = j;
    bool found = false;
    for (int w8 = 0; w8 <= (wmax >> 5) && !found; w8++) {
        uint32_t nzw = g_nz[w8][j];
        if (w8 == (wmax >> 5)) {
            int hib = wmax & 31;
            nzw &= (hib == 31) ? 0xffffffffu : ((2u << hib) - 1u);
        }
        while (nzw) {
            int b = __ffs(nzw) - 1; nzw &= nzw - 1;
            int w = (w8 << 5) + b;
            uint32_t m = g_adjT[w][j] & hh[w];
            if (m) { cfound = (w << 5) + __ffs(m) - 1; found = true; break; }
        }
    }
    g_cluster[j] = cfound;
    atomicAdd(&g_cnt[cfound], 1);
    atomicAdd(&g_prob[cfound], g_s[j]);
    atomicMax(&g_y2bits[cfound], __float_as_uint(g_by2[j]));   // by2 >= 0 -> bit-ordered
}

// ---------------- K6: first pick per cluster ------------------------------------
__global__ void k_first(int n)
{
    int j = blockIdx.x * blockDim.x + threadIdx.x;
    if (j >= n) return;
    int c = g_cluster[j];
    float mx = __uint_as_float(g_y2bits[c]);
    if (g_by2[j] >= mx) atomicMin(&g_first[c], j);
}

// ---------------- K7: write output ----------------------------------------------
__global__ void k_out(float* __restrict__ out, int n, int out_size)
{
    int i = blockIdx.x * blockDim.x + threadIdx.x;
    if (i < n) {
        int c = g_cluster[i];
        float nmf = (float)g_nm;
        bool keep = (i == g_first[c]) && ((float)g_cnt[c] >= nmf / 3.0f);
        float so = g_prob[c] / nmf;
        float4 b = g_obox[i];
        out[i * 5 + 0] = keep ? b.x : 0.0f;
        out[i * 5 + 1] = keep ? b.y : 0.0f;
        out[i * 5 + 2] = keep ? b.z : 0.0f;
        out[i * 5 + 3] = keep ? b.w : 0.0f;
        out[i * 5 + 4] = keep ? so : 0.0f;
        if (out_size >= 6 * n) out[5 * n + i] = keep ? 1.0f : 0.0f;
    }
    int stride = gridDim.x * blockDim.x;
    for (int t = 6 * n + i; t < out_size; t += stride) out[t] = 0.0f;
}

// ---------------- launcher -------------------------------------------------------
extern "C" void kernel_launch(void* const* d_in, const int* in_sizes, int n_in,
                              void* d_out, int out_size)
{
    const float* boxes  = (const float*)d_in[0];
    const float* scores = (const float*)d_in[1];
    const void*  nmp    = d_in[2];
    int n = in_sizes[1];
    if (n > NMAX) n = NMAX;

    int nb = (n + 255) / 256;
    k_prep<<<nb, 256>>>(scores, nmp, n);
    dim3 rg((n + 255) / 256, (n + 1023) / 1024);
    k_rank<<<rg, 256>>>(n);
    k_gather<<<nb, 256>>>(boxes, scores, n);

    int rowTiles = (n + 127) / 128;
    int tiles = 0;
    for (int rt = 0; rt < rowTiles; rt++) tiles += (rt >> 3) + 1;
    k_adj<<<tiles, 256>>>(n);

    k_scan<<<1, 1024>>>(n);
    k_assign<<<nb, 256>>>(n);
    k_first<<<nb, 256>>>(n);
    k_out<<<nb, 256>>>((float*)d_out, n, out_size);
}

// round 3
// speedup vs baseline: 2.7018x; 1.4869x over previous
#include <cuda_runtime.h>
#include <stdint.h>

#define NMAX 8192
#define WORDS 256          /* NMAX/32 */
#define CAP   256          /* max entries per row == WORDS -> always complete */
#define RREG  8            /* entries cached in registers in k_scan */
#define W_IMG 1920.0f
#define H_IMG 1080.0f

// ---------------- device scratch ----------------
__device__ int g_rankp[8][NMAX];
__device__ unsigned long long g_elist[NMAX][CAP];   // (word<<32)|bits, bits strictly below row
__device__ int g_ecnt[NMAX];
__device__ float4 g_abox[NMAX];               // clipped x1,y1,x2+1,y2+1
__device__ float4 g_obox[NMAX];               // clipped x1,y1,x2,y2
__device__ float g_s[NMAX], g_area[NMAX], g_by2[NMAX];
__device__ uint32_t g_head[WORDS];
__device__ int g_cluster[NMAX];
__device__ int g_cnt[NMAX];
__device__ float g_prob[NMAX];
__device__ uint32_t g_y2bits[NMAX];
__device__ int g_first[NMAX];
__device__ int g_nm;

__device__ __forceinline__ unsigned long long skey(const float* __restrict__ s, int i)
{
    return (((unsigned long long)(~__float_as_uint(s[i]))) << 32) | (uint32_t)i;
}

// ---------------- K1: O(n^2) partial rank (no atomics, no init) ----------------
__global__ void k_rank(const float* __restrict__ scores, int n)
{
    __shared__ unsigned long long sk[1024];
    int base = blockIdx.y * 1024;
    for (int t = threadIdx.x; t < 1024; t += 256)
        sk[t] = (base + t < n) ? skey(scores, base + t) : 0xFFFFFFFFFFFFFFFFULL;
    __syncthreads();
    int i = blockIdx.x * 256 + threadIdx.x;
    if (i >= n) return;
    unsigned long long a = skey(scores, i);
    int cnt = 0;
    #pragma unroll 8
    for (int q = 0; q < 1024; q++) cnt += (sk[q] < a);
    g_rankp[blockIdx.y][i] = cnt;
}

// ---------------- K2: scatter into sorted order + all per-index init -----------
__global__ void k_gather(const float* __restrict__ boxes, const float* __restrict__ scores,
                         const void* __restrict__ nmp, int n, int slices)
{
    int i = blockIdx.x * blockDim.x + threadIdx.x;
    if (i >= n) return;
    int r = 0;
    for (int k = 0; k < slices; k++) r += g_rankp[k][i];
    float x1 = boxes[i * 4 + 0], y1 = boxes[i * 4 + 1];
    float x2 = boxes[i * 4 + 2], y2 = boxes[i * 4 + 3];
    x1 = fminf(fmaxf(x1, 0.0f), W_IMG);
    y1 = fminf(fmaxf(y1, 0.0f), H_IMG);
    x2 = fminf(fmaxf(x2, 0.0f), W_IMG);
    y2 = fminf(fmaxf(y2, 0.0f), H_IMG);
    g_obox[r] = make_float4(x1, y1, x2, y2);
    g_abox[r] = make_float4(x1, y1, x2 + 1.0f, y2 + 1.0f);
    g_by2[r] = y2;
    g_s[r] = scores[i];
    g_area[r] = ((x2 - x1) + 1.0f) * ((y2 - y1) + 1.0f);
    // per-index init (i is a permutation cover)
    g_ecnt[i] = 0; g_cnt[i] = 0; g_prob[i] = 0.0f; g_y2bits[i] = 0u; g_first[i] = n;
    #pragma unroll
    for (int q = 0; q < RREG; q++) g_elist[i][q] = 0ULL;
    if (i == 0) {
        int iv = ((const int*)nmp)[0];
        float fv = ((const float*)nmp)[0];
        g_nm = (iv > 0 && iv < 1000000) ? iv : (int)fv;
    }
}

// ---------------- K3: lower-triangle adjacency -> sparse edge list -------------
// tile = 64 rows x 512 cols; 256 threads (8 warps x 8 rows)
__global__ void __launch_bounds__(256) k_adj(int n)
{
    int rem = blockIdx.x, rt = 0;
    for (;;) { int cnt = (rt >> 3) + 1; if (rem < cnt) break; rem -= cnt; rt++; }
    int rowBase = rt * 64, colBase = rem * 512;

    __shared__ float4 cb[512]; __shared__ float ca[512];
    __shared__ float4 rb[64];  __shared__ float ra[64];

    for (int t = threadIdx.x; t < 512; t += 256) {
        int c = colBase + t;
        if (c < n) { cb[t] = g_abox[c]; ca[t] = g_area[c]; }
        else       { cb[t] = make_float4(2e9f, 2e9f, -2e9f, -2e9f); ca[t] = 1.0f; }
    }
    for (int t = threadIdx.x; t < 64; t += 256) {
        int r = rowBase + t; if (r >= n) r = n - 1;
        rb[t] = g_abox[r]; ra[t] = g_area[r];
    }
    __syncthreads();

    int warp = threadIdx.x >> 5, lane = threadIdx.x & 31;
    int rl0 = warp * 8;

    for (int grp = 0; grp < 2; grp++) {
        int rl = rl0 + grp * 4;
        float4 A[4]; float aa[4];
        #pragma unroll
        for (int k = 0; k < 4; k++) { A[k] = rb[rl + k]; aa[k] = ra[rl + k]; }
        int row0 = rowBase + rl;
        for (int wi = 0; wi < 16; wi++) {
            int cwb = colBase + wi * 32;
            if (cwb > row0 + 3) continue;              // fully above diagonal (warp-uniform)
            float4 B = cb[wi * 32 + lane];
            float ab = ca[wi * 32 + lane];
            int gw = (colBase >> 5) + wi;
            #pragma unroll
            for (int k = 0; k < 4; k++) {
                int row = row0 + k;
                if (cwb > row || row >= n) continue;   // warp-uniform
                float w = fmaxf(fminf(A[k].z, B.z) - fmaxf(A[k].x, B.x), 0.0f);
                float h = fmaxf(fminf(A[k].w, B.w) - fmaxf(A[k].y, B.y), 0.0f);
                float inter = w * h;
                float den = (aa[k] + ab) - inter;
                unsigned bits = __ballot_sync(0xffffffffu, inter + inter > den);
                int d = row - cwb;
                if (d < 32) bits &= (1u << d) - 1u;    // strictly below row (kills self bit)
                if (lane == 0 && bits) {
                    int pos = atomicAdd(&g_ecnt[row], 1);
                    if (pos < CAP)
                        g_elist[row][pos] = ((unsigned long long)gw << 32) | bits;
                }
            }
        }
    }
}

// ---------------- K4: head resolution (1 block, 128 threads, reg-pipelined) ----
__global__ void __launch_bounds__(128) k_scan(int n)
{
    __shared__ uint32_t headb[WORDS];
    __shared__ uint32_t actw[4], confw[4];
    __shared__ uint32_t sla[128][4];

    int tid = threadIdx.x;
    for (int t = tid; t < WORDS; t += 128) headb[t] = 0u;

    // prefetch chunk 0
    int pcnt = 0; unsigned long long pe[RREG];
    #pragma unroll
    for (int q = 0; q < RREG; q++) pe[q] = 0ULL;
    if (tid < n) {
        pcnt = g_ecnt[tid];
        #pragma unroll
        for (int q = 0; q < RREG; q++) pe[q] = g_elist[tid][q];
    }
    __syncthreads();

    int chunks = (n + 127) >> 7;
    for (int c = 0; c < chunks; c++) {
        int j = (c << 7) + tid;
        int mycnt = pcnt;
        unsigned long long e[RREG];
        #pragma unroll
        for (int q = 0; q < RREG; q++) e[q] = pe[q];

        // classify entries: earlier-chunk words vs in-chunk words
        uint32_t base_w = (uint32_t)(c << 2);
        uint32_t hit_ext = 0u;
        uint32_t inw0 = 0u, inw1 = 0u, inw2 = 0u, inw3 = 0u;
        #pragma unroll
        for (int q = 0; q < RREG; q++) {
            uint32_t w = (uint32_t)(e[q] >> 32), v = (uint32_t)e[q];
            if (w < base_w) hit_ext |= v & headb[w];
            else {
                uint32_t dw = w - base_w;
                if (dw == 0u) inw0 |= v; else if (dw == 1u) inw1 |= v;
                else if (dw == 2u) inw2 |= v; else inw3 |= v;
            }
        }
        if (mycnt > RREG) {
            int lim = mycnt < CAP ? mycnt : CAP;
            for (int q = RREG; q < lim; q++) {
                unsigned long long eo = g_elist[j][q];
                uint32_t w = (uint32_t)(eo >> 32), v = (uint32_t)eo;
                if (w < base_w) hit_ext |= v & headb[w];
                else {
                    uint32_t dw = w - base_w;
                    if (dw == 0u) inw0 |= v; else if (dw == 1u) inw1 |= v;
                    else if (dw == 2u) inw2 |= v; else inw3 |= v;
                }
            }
        }

        // issue next-chunk prefetch (consumed next iteration -> latency hidden)
        {
            int jn = j + 128;
            pcnt = 0;
            #pragma unroll
            for (int q = 0; q < RREG; q++) pe[q] = 0ULL;
            if (jn < n) {
                pcnt = g_ecnt[jn];
                #pragma unroll
                for (int q = 0; q < RREG; q++) pe[q] = g_elist[jn][q];
            }
        }

        bool active = (j < n) && (hit_ext == 0u);
        sla[tid][0] = inw0; sla[tid][1] = inw1; sla[tid][2] = inw2; sla[tid][3] = inw3;
        uint32_t ab = __ballot_sync(0xffffffffu, active);
        if ((tid & 31) == 0) actw[tid >> 5] = ab;
        __syncthreads();

        uint32_t hit_in = (inw0 & actw[0]) | (inw1 & actw[1]) | (inw2 & actw[2]) | (inw3 & actw[3]);
        bool conf = active && (hit_in != 0u);
        uint32_t cb2 = __ballot_sync(0xffffffffu, conf);
        if ((tid & 31) == 0) confw[tid >> 5] = cb2;
        __syncthreads();

        if (tid == 0) {
            uint32_t h[4];
            #pragma unroll
            for (int k = 0; k < 4; k++) h[k] = actw[k] & ~confw[k];
            for (int k = 0; k < 4; k++) {
                uint32_t m = confw[k];
                while (m) {
                    int b = __ffs(m) - 1; m &= m - 1;
                    int jj = k * 32 + b;
                    uint32_t hit = (sla[jj][0] & h[0]) | (sla[jj][1] & h[1])
                                 | (sla[jj][2] & h[2]) | (sla[jj][3] & h[3]);
                    if (!hit) h[k] |= 1u << b;
                }
            }
            #pragma unroll
            for (int k = 0; k < 4; k++) headb[base_w + k] = h[k];
        }
        __syncthreads();
    }
    for (int t = tid; t < WORDS; t += 128) g_head[t] = headb[t];
}

// ---------------- K5: cluster assignment via edge list -------------------------
__global__ void k_assign(int n)
{
    __shared__ uint32_t hh[WORDS];
    for (int t = threadIdx.x; t < WORDS; t += blockDim.x) hh[t] = g_head[t];
    __syncthreads();
    int j = blockIdx.x * blockDim.x + threadIdx.x;
    if (j >= n) return;
    int cnt = g_ecnt[j]; if (cnt > CAP) cnt = CAP;
    int best = 0x7fffffff;
    for (int q = 0; q < cnt; q++) {
        unsigned long long e = g_elist[j][q];
        uint32_t w = (uint32_t)(e >> 32);
        uint32_t m = ((uint32_t)e) & hh[w];
        if (m) { int cand = ((int)w << 5) + __ffs(m) - 1; if (cand < best) best = cand; }
    }
    int cf = (best == 0x7fffffff) ? j : best;
    g_cluster[j] = cf;
    atomicAdd(&g_cnt[cf], 1);
    atomicAdd(&g_prob[cf], g_s[j]);
    atomicMax(&g_y2bits[cf], __float_as_uint(g_by2[j]));   // by2 >= 0 -> bit-ordered
}

// ---------------- K6: first pick per cluster ------------------------------------
__global__ void k_first(int n)
{
    int j = blockIdx.x * blockDim.x + threadIdx.x;
    if (j >= n) return;
    int c = g_cluster[j];
    float mx = __uint_as_float(g_y2bits[c]);
    if (g_by2[j] >= mx) atomicMin(&g_first[c], j);
}

// ---------------- K7: write output ----------------------------------------------
__global__ void k_out(float* __restrict__ out, int n, int out_size)
{
    int i = blockIdx.x * blockDim.x + threadIdx.x;
    if (i < n) {
        int c = g_cluster[i];
        float nmf = (float)g_nm;
        bool keep = (i == g_first[c]) && ((float)g_cnt[c] >= nmf / 3.0f);
        float so = g_prob[c] / nmf;
        float4 b = g_obox[i];
        out[i * 5 + 0] = keep ? b.x : 0.0f;
        out[i * 5 + 1] = keep ? b.y : 0.0f;
        out[i * 5 + 2] = keep ? b.z : 0.0f;
        out[i * 5 + 3] = keep ? b.w : 0.0f;
        out[i * 5 + 4] = keep ? so : 0.0f;
        if (out_size >= 6 * n) out[5 * n + i] = keep ? 1.0f : 0.0f;
    }
    int stride = gridDim.x * blockDim.x;
    for (int t = 6 * n + i; t < out_size; t += stride) out[t] = 0.0f;
}

// ---------------- launcher -------------------------------------------------------
extern "C" void kernel_launch(void* const* d_in, const int* in_sizes, int n_in,
                              void* d_out, int out_size)
{
    const float* boxes  = (const float*)d_in[0];
    const float* scores = (const float*)d_in[1];
    const void*  nmp    = d_in[2];
    int n = in_sizes[1];
    if (n > NMAX) n = NMAX;

    int nb = (n + 255) / 256;
    int slices = (n + 1023) / 1024;
    dim3 rg(nb, slices);
    k_rank<<<rg, 256>>>(scores, n);
    k_gather<<<nb, 256>>>(boxes, scores, nmp, n, slices);

    int rowTiles = (n + 63) / 64;
    int tiles = 0;
    for (int rt = 0; rt < rowTiles; rt++) tiles += (rt >> 3) + 1;
    k_adj<<<tiles, 256>>>(n);

    k_scan<<<1, 128>>>(n);
    k_assign<<<nb, 256>>>(n);
    k_first<<<nb, 256>>>(n);
    k_out<<<nb, 256>>>((float*)d_out, n, out_size);
}